// round 2
// baseline (speedup 1.0000x reference)
#include <cuda_runtime.h>

// GptOssTopKRouter: logits = hs[16384,2880] @ w[128,2880]^T + bias[128]
// -> top-4 -> softmax over selected. Output f32: scores[T*4] ++ indices[T*4].
//
// Accuracy: per-chunk fresh accumulators (chain 32) + Kahan compensated
// level-1 summation (rounding-mode intrinsics defeat reassociation).

#define TT   16384
#define HH   2880
#define EE   128
#define TOPK 4

#define BM 64
#define BN 128
#define BK 32
#define NCHUNK (HH / BK)   // 90
#define PAD 4

__global__ __launch_bounds__(256)
void router_kernel(const float* __restrict__ hs,
                   const float* __restrict__ wt,
                   const float* __restrict__ bias,
                   float* __restrict__ out,
                   int write_idx)
{
    __shared__ float sA[BK][BM + PAD];     // sA[k][m]
    __shared__ float sB[BK][BN + PAD];     // sB[k][n]
    __shared__ float sL[BM * BN];          // logits

    const int tid = threadIdx.x;
    const int tx  = tid & 15;              // 8 experts each
    const int ty  = tid >> 4;              // 4 tokens each
    const int m0  = blockIdx.x * BM;

    float sum_[4][8], cmp_[4][8];
    #pragma unroll
    for (int i = 0; i < 4; i++)
        #pragma unroll
        for (int j = 0; j < 8; j++) { sum_[i][j] = 0.0f; cmp_[i][j] = 0.0f; }

    for (int kc = 0; kc < NCHUNK; kc++) {
        const int k0 = kc * BK;

        // ---- global loads (issue before barrier) ----
        float4 av[2], bv[4];
        #pragma unroll
        for (int r = 0; r < 2; r++) {
            int s   = tid + 256 * r;       // 512 A slots
            int row = s >> 3;
            int kq  = s & 7;
            av[r] = *reinterpret_cast<const float4*>(
                        &hs[(size_t)(m0 + row) * HH + k0 + kq * 4]);
        }
        #pragma unroll
        for (int r = 0; r < 4; r++) {
            int s   = tid + 256 * r;       // 1024 B slots
            int row = s >> 3;
            int kq  = s & 7;
            bv[r] = *reinterpret_cast<const float4*>(
                        &wt[(size_t)row * HH + k0 + kq * 4]);
        }

        __syncthreads();                   // prior chunk compute done

        #pragma unroll
        for (int r = 0; r < 2; r++) {
            int s   = tid + 256 * r;
            int row = s >> 3;
            int kq  = s & 7;
            sA[kq * 4 + 0][row] = av[r].x;
            sA[kq * 4 + 1][row] = av[r].y;
            sA[kq * 4 + 2][row] = av[r].z;
            sA[kq * 4 + 3][row] = av[r].w;
        }
        #pragma unroll
        for (int r = 0; r < 4; r++) {
            int s   = tid + 256 * r;
            int row = s >> 3;
            int kq  = s & 7;
            sB[kq * 4 + 0][row] = bv[r].x;
            sB[kq * 4 + 1][row] = bv[r].y;
            sB[kq * 4 + 2][row] = bv[r].z;
            sB[kq * 4 + 3][row] = bv[r].w;
        }

        __syncthreads();

        // ---- fresh chunk accumulator: short rounding chain ----
        float ch[4][8];
        #pragma unroll
        for (int i = 0; i < 4; i++)
            #pragma unroll
            for (int j = 0; j < 8; j++) ch[i][j] = 0.0f;

        #pragma unroll
        for (int k = 0; k < BK; k++) {
            float4 a4  = *reinterpret_cast<const float4*>(&sA[k][ty * 4]);
            float4 b40 = *reinterpret_cast<const float4*>(&sB[k][tx * 8]);
            float4 b41 = *reinterpret_cast<const float4*>(&sB[k][tx * 8 + 4]);
            float ar[4] = {a4.x, a4.y, a4.z, a4.w};
            float br[8] = {b40.x, b40.y, b40.z, b40.w,
                           b41.x, b41.y, b41.z, b41.w};
            #pragma unroll
            for (int i = 0; i < 4; i++)
                #pragma unroll
                for (int j = 0; j < 8; j++)
                    ch[i][j] = fmaf(ar[i], br[j], ch[i][j]);
        }

        // ---- Kahan fold into running sum ----
        #pragma unroll
        for (int i = 0; i < 4; i++)
            #pragma unroll
            for (int j = 0; j < 8; j++) {
                float y = __fsub_rn(ch[i][j], cmp_[i][j]);
                float t = __fadd_rn(sum_[i][j], y);
                cmp_[i][j] = __fsub_rn(__fsub_rn(t, sum_[i][j]), y);
                sum_[i][j] = t;
            }
    }

    // Bias add + logits to SMEM (apply final Kahan correction).
    float bvreg[8];
    #pragma unroll
    for (int j = 0; j < 8; j++) bvreg[j] = bias[tx * 8 + j];

    #pragma unroll
    for (int i = 0; i < 4; i++)
        #pragma unroll
        for (int j = 0; j < 8; j++) {
            float v = __fsub_rn(sum_[i][j], cmp_[i][j]);
            sL[(ty * 4 + i) * BN + tx * 8 + j] = v + bvreg[j];
        }

    __syncthreads();

    // Top-4 + softmax: one thread per token.
    if (tid < BM) {
        const float* row = &sL[tid * BN];
        float v0 = -1e30f, v1 = -1e30f, v2 = -1e30f, v3 = -1e30f;
        int   i0 = 0,      i1 = 0,      i2 = 0,      i3 = 0;
        #pragma unroll 4
        for (int e = 0; e < EE; e++) {
            float v = row[e];
            if (v > v3) {
                if (v > v2) {
                    v3 = v2; i3 = i2;
                    if (v > v1) {
                        v2 = v1; i2 = i1;
                        if (v > v0) { v1 = v0; i1 = i0; v0 = v; i0 = e; }
                        else        { v1 = v;  i1 = e; }
                    } else { v2 = v; i2 = e; }
                } else { v3 = v; i3 = e; }
            }
        }
        float e1 = expf(v1 - v0);
        float e2 = expf(v2 - v0);
        float e3 = expf(v3 - v0);
        float inv = 1.0f / (1.0f + e1 + e2 + e3);

        const int t = m0 + tid;
        float* so = out + (size_t)t * TOPK;
        so[0] = inv;
        so[1] = e1 * inv;
        so[2] = e2 * inv;
        so[3] = e3 * inv;

        if (write_idx) {
            float* io = out + (size_t)TT * TOPK + (size_t)t * TOPK;
            io[0] = (float)i0;
            io[1] = (float)i1;
            io[2] = (float)i2;
            io[3] = (float)i3;
        }
    }
}

extern "C" void kernel_launch(void* const* d_in, const int* in_sizes, int n_in,
                              void* d_out, int out_size) {
    const float* hs   = (const float*)d_in[0];
    const float* wt   = (const float*)d_in[1];
    const float* bias = (const float*)d_in[2];
    float* out = (float*)d_out;

    const int write_idx = (out_size >= 2 * TT * TOPK) ? 1 : 0;

    router_kernel<<<TT / BM, 256>>>(hs, wt, bias, out, write_idx);
}

// round 4
// speedup vs baseline: 1.8204x; 1.8204x over previous
#include <cuda_runtime.h>

// GptOssTopKRouter: logits = hs[16384,2880] @ w[128,2880]^T + bias[128]
// -> top-4 -> softmax. Output f32: scores[T*4] ++ indices[T*4].
//
// R4 (= R3 resubmit after infra failure): packed fma.rn.f32x2 (2x fp32 FMA
// rate on sm_103a, PTX-only) + 128x128 CTA tile with 8x8-per-thread register
// blocking (1.0 B LDS/FMA). Accuracy: fresh per-chunk accumulators (32-long
// chains) folded with plain f32x2 adds (two-level summation).

#define TT   16384
#define HH   2880
#define EE   128
#define TOPK 4

#define BM 128
#define BN 128
#define BK 32
#define NCHUNK (HH / BK)     // 90
#define APITCH 132           // BM + 4 pad (16B-aligned rows)
#define LPITCH 132

typedef unsigned long long ull;

__device__ __forceinline__ ull fma2(ull a, ull b, ull c) {
    ull d;
    asm("fma.rn.f32x2 %0, %1, %2, %3;" : "=l"(d) : "l"(a), "l"(b), "l"(c));
    return d;
}
__device__ __forceinline__ ull add2(ull a, ull b) {
    ull d;
    asm("add.rn.f32x2 %0, %1, %2;" : "=l"(d) : "l"(a), "l"(b));
    return d;
}
__device__ __forceinline__ ull dup2(float x) {
    ull d;
    asm("mov.b64 %0, {%1, %1};" : "=l"(d) : "f"(x));
    return d;
}
__device__ __forceinline__ void unpack2(ull v, float& lo, float& hi) {
    asm("mov.b64 {%0, %1}, %2;" : "=f"(lo), "=f"(hi) : "l"(v));
}

__global__ __launch_bounds__(256, 1)
void router_kernel(const float* __restrict__ hs,
                   const float* __restrict__ wt,
                   const float* __restrict__ bias,
                   float* __restrict__ out,
                   int write_idx)
{
    extern __shared__ float smem[];
    float (*sA)[APITCH] = reinterpret_cast<float (*)[APITCH]>(smem);              // [BK][APITCH]
    float (*sB)[APITCH] = reinterpret_cast<float (*)[APITCH]>(smem + BK * APITCH);
    float (*sL)[LPITCH] = reinterpret_cast<float (*)[LPITCH]>(smem + 2 * BK * APITCH);

    const int tid = threadIdx.x;
    const int tx  = tid & 15;            // expert group: experts tx*8 .. +7
    const int ty  = tid >> 4;            // token group:  tokens  ty*8 .. +7
    const int m0  = blockIdx.x * BM;

    ull sum_[32];                        // 8 rows x 4 f32x2 (8 experts)
    #pragma unroll
    for (int i = 0; i < 32; i++) sum_[i] = 0ull;

    for (int kc = 0; kc < NCHUNK; kc++) {
        const int k0 = kc * BK;

        // ---- global loads (issued before the barrier to overlap compute) ----
        float4 av[4], bv[4];
        #pragma unroll
        for (int r = 0; r < 4; r++) {
            int s   = tid + 256 * r;     // 1024 float4 slots per tile
            int row = s >> 3;
            int kq  = s & 7;
            av[r] = *reinterpret_cast<const float4*>(
                        &hs[(size_t)(m0 + row) * HH + k0 + kq * 4]);
            bv[r] = *reinterpret_cast<const float4*>(
                        &wt[(size_t)row * HH + k0 + kq * 4]);
        }

        __syncthreads();                 // previous chunk compute done

        #pragma unroll
        for (int r = 0; r < 4; r++) {
            int s   = tid + 256 * r;
            int row = s >> 3;
            int kq  = s & 7;
            sA[kq * 4 + 0][row] = av[r].x;
            sA[kq * 4 + 1][row] = av[r].y;
            sA[kq * 4 + 2][row] = av[r].z;
            sA[kq * 4 + 3][row] = av[r].w;
            sB[kq * 4 + 0][row] = bv[r].x;
            sB[kq * 4 + 1][row] = bv[r].y;
            sB[kq * 4 + 2][row] = bv[r].z;
            sB[kq * 4 + 3][row] = bv[r].w;
        }

        __syncthreads();

        // ---- fresh chunk accumulator (short rounding chain of 32) ----
        ull ch[32];
        #pragma unroll
        for (int i = 0; i < 32; i++) ch[i] = 0ull;

        #pragma unroll
        for (int k = 0; k < BK; k++) {
            ulonglong2 B0 = *reinterpret_cast<const ulonglong2*>(&sB[k][tx * 8]);
            ulonglong2 B1 = *reinterpret_cast<const ulonglong2*>(&sB[k][tx * 8 + 4]);
            ull bb[4] = {B0.x, B0.y, B1.x, B1.y};

            float4 A0 = *reinterpret_cast<const float4*>(&sA[k][ty * 8]);
            float4 A1 = *reinterpret_cast<const float4*>(&sA[k][ty * 8 + 4]);
            float ar[8] = {A0.x, A0.y, A0.z, A0.w, A1.x, A1.y, A1.z, A1.w};

            #pragma unroll
            for (int i = 0; i < 8; i++) {
                ull ad = dup2(ar[i]);
                #pragma unroll
                for (int j = 0; j < 4; j++)
                    ch[i * 4 + j] = fma2(ad, bb[j], ch[i * 4 + j]);
            }
        }

        // ---- fold chunk into running sum (level-1 chain of 90) ----
        #pragma unroll
        for (int i = 0; i < 32; i++) sum_[i] = add2(sum_[i], ch[i]);
    }

    // ---- bias + logits to SMEM ----
    float bvreg[8];
    #pragma unroll
    for (int j = 0; j < 8; j++) bvreg[j] = bias[tx * 8 + j];

    __syncthreads();   // all LDS reads of sA/sB done before sL writes race nothing

    #pragma unroll
    for (int i = 0; i < 8; i++)
        #pragma unroll
        for (int j = 0; j < 4; j++) {
            float lo, hi;
            unpack2(sum_[i * 4 + j], lo, hi);
            sL[ty * 8 + i][tx * 8 + j * 2 + 0] = lo + bvreg[j * 2 + 0];
            sL[ty * 8 + i][tx * 8 + j * 2 + 1] = hi + bvreg[j * 2 + 1];
        }

    __syncthreads();

    // ---- top-4 + softmax: one thread per token (threads 0..127) ----
    if (tid < BM) {
        const float* row = sL[tid];
        float v0 = -1e30f, v1 = -1e30f, v2 = -1e30f, v3 = -1e30f;
        int   i0 = 0,      i1 = 0,      i2 = 0,      i3 = 0;
        #pragma unroll 4
        for (int e = 0; e < EE; e++) {
            float v = row[e];
            if (v > v3) {               // strict > keeps earliest index on ties
                if (v > v2) {
                    v3 = v2; i3 = i2;
                    if (v > v1) {
                        v2 = v1; i2 = i1;
                        if (v > v0) { v1 = v0; i1 = i0; v0 = v; i0 = e; }
                        else        { v1 = v;  i1 = e; }
                    } else { v2 = v; i2 = e; }
                } else { v3 = v; i3 = e; }
            }
        }
        float e1 = expf(v1 - v0);
        float e2 = expf(v2 - v0);
        float e3 = expf(v3 - v0);
        float inv = 1.0f / (1.0f + e1 + e2 + e3);

        const int t = m0 + tid;
        float* so = out + (size_t)t * TOPK;
        so[0] = inv;
        so[1] = e1 * inv;
        so[2] = e2 * inv;
        so[3] = e3 * inv;

        if (write_idx) {
            float* io = out + (size_t)TT * TOPK + (size_t)t * TOPK;
            io[0] = (float)i0;
            io[1] = (float)i1;
            io[2] = (float)i2;
            io[3] = (float)i3;
        }
    }
}

extern "C" void kernel_launch(void* const* d_in, const int* in_sizes, int n_in,
                              void* d_out, int out_size) {
    const float* hs   = (const float*)d_in[0];
    const float* wt   = (const float*)d_in[1];
    const float* bias = (const float*)d_in[2];
    float* out = (float*)d_out;

    const int write_idx = (out_size >= 2 * TT * TOPK) ? 1 : 0;

    const int smem_bytes = (2 * BK * APITCH + BM * LPITCH) * sizeof(float);
    cudaFuncSetAttribute(router_kernel,
                         cudaFuncAttributeMaxDynamicSharedMemorySize, smem_bytes);

    router_kernel<<<TT / BM, 256, smem_bytes>>>(hs, wt, bias, out, write_idx);
}

// round 6
// speedup vs baseline: 2.7130x; 1.4904x over previous
#include <cuda_runtime.h>
#include <cstdint>

// GptOssTopKRouter via legacy tensor-core path (mma.sync bf16, compiles for
// compute_103 — tcgen05 PTX is rejected by this harness's virtual arch).
// logits = hs[16384,2880] @ w[128,2880]^T + bias -> top-4 -> softmax.
// Output f32: scores[T*4] ++ indices[T*4].
//
// fp32 emulated by 3-plane bf16 Dekker split with 6 plane-product MMAs.
// Main product (a0b0) accumulates in its own fp32 register set (180-add
// chain, sigma~2.7e-7); the 5 small correction products accumulate in a
// second set (negligible rounding). Matches R4's proven noise level.

#define TT    16384
#define HH    2880
#define EE    128
#define TOPK  4
#define BM    128
#define KC    16
#define NCH   (HH / KC)        // 180

#define PITCH  48              // bytes per row in a bf16 plane (24 bf16)
#define PLB    (128 * PITCH)   // 6144 B per plane
#define SM_PLANE 512           // planes: A0 A1 A2 B0 B1 B2 -> 512..37376
#define LPITCH 132
#define SMEM_BYTES (512 + BM * LPITCH * 4)   // 68096 (logits reuse plane area)

__device__ __forceinline__ uint32_t s2u(const void* p) {
    uint32_t a;
    asm("{ .reg .u64 t; cvta.to.shared.u64 t, %1; cvt.u32.u64 %0, t; }"
        : "=r"(a) : "l"(p));
    return a;
}
__device__ __forceinline__ uint32_t pack_bf16x2(float hi, float lo) {
    uint32_t r;
    asm("cvt.rn.bf16x2.f32 %0, %1, %2;" : "=r"(r) : "f"(hi), "f"(lo));
    return r;
}
__device__ __forceinline__ void ldmx4(uint32_t* r, uint32_t addr) {
    asm volatile("ldmatrix.sync.aligned.m8n8.x4.shared.b16 {%0,%1,%2,%3}, [%4];"
                 : "=r"(r[0]), "=r"(r[1]), "=r"(r[2]), "=r"(r[3]) : "r"(addr));
}
__device__ __forceinline__ void mma16(float* c, const uint32_t* a, const uint32_t* b) {
    asm("mma.sync.aligned.m16n8k16.row.col.f32.bf16.bf16.f32 "
        "{%0,%1,%2,%3}, {%4,%5,%6,%7}, {%8,%9}, {%0,%1,%2,%3};"
        : "+f"(c[0]), "+f"(c[1]), "+f"(c[2]), "+f"(c[3])
        : "r"(a[0]), "r"(a[1]), "r"(a[2]), "r"(a[3]), "r"(b[0]), "r"(b[1]));
}

// Convert 8 fp32 -> 3 bf16 planes (Dekker: a = a0 + a1 + a2 exactly in fp32,
// last plane rounded at 2^-27 relative). Each plane gets one 16B store.
__device__ __forceinline__ void cvt8(const float4& f0, const float4& f1,
                                     char* p0, char* p1, char* p2) {
    float x[8] = {f0.x, f0.y, f0.z, f0.w, f1.x, f1.y, f1.z, f1.w};
    uint32_t q0[4], q1[4], q2[4];
    #pragma unroll
    for (int q = 0; q < 4; q++) {
        float a = x[2 * q], b = x[2 * q + 1];
        uint32_t h = pack_bf16x2(b, a);             // lo=bf16(a), hi=bf16(b)
        float ha = __uint_as_float(h << 16);
        float hb = __uint_as_float(h & 0xFFFF0000u);
        float ra = a - ha, rb = b - hb;             // exact (Sterbenz)
        uint32_t m = pack_bf16x2(rb, ra);
        float ma = __uint_as_float(m << 16);
        float mb = __uint_as_float(m & 0xFFFF0000u);
        float sa = ra - ma, sb = rb - mb;           // exact
        q2[q] = pack_bf16x2(sb, sa);
        q0[q] = h; q1[q] = m;
    }
    *reinterpret_cast<uint4*>(p0) = make_uint4(q0[0], q0[1], q0[2], q0[3]);
    *reinterpret_cast<uint4*>(p1) = make_uint4(q1[0], q1[1], q1[2], q1[3]);
    *reinterpret_cast<uint4*>(p2) = make_uint4(q2[0], q2[1], q2[2], q2[3]);
}

__global__ __launch_bounds__(256, 1)
void router_hmma(const float* __restrict__ hs,
                 const float* __restrict__ wt,
                 const float* __restrict__ bias,
                 float* __restrict__ out,
                 int write_idx)
{
    extern __shared__ char smem[];
    float* sbias = reinterpret_cast<float*>(smem);
    float* slog  = reinterpret_cast<float*>(smem + SM_PLANE);
    const uint32_t sb = s2u(smem);

    const int tid  = threadIdx.x;
    const int wid  = tid >> 5;
    const int lane = tid & 31;
    const int m0   = blockIdx.x * BM;

    if (tid < EE) sbias[tid] = bias[tid];

    // ---- convert-phase mapping: 2 threads per row, 8 fp32 each ----
    const int crow = tid >> 1;
    const int ckh  = (tid & 1) * 8;
    const float* gA = hs + (size_t)(m0 + crow) * HH + ckh;
    const float* gB = wt + (size_t)crow * HH + ckh;
    char* pA = smem + SM_PLANE + crow * PITCH + ckh * 2;
    char* pB = smem + SM_PLANE + 3 * PLB + crow * PITCH + ckh * 2;

    // ---- mma-phase mapping: warp = (4 M) x (2 N); warp tile 32x64 ----
    const int moff = (wid >> 1) * 32;
    const int noff = (wid & 1) * 64;
    const int mt8  = lane >> 3;        // ldmatrix sub-matrix id
    const int mr   = lane & 7;
    uint32_t aoff[2], boff[4];
    #pragma unroll
    for (int mt = 0; mt < 2; mt++) {
        int row  = moff + mt * 16 + ((mt8 & 1) << 3) + mr;
        int kcol = (mt8 >> 1) << 3;
        aoff[mt] = (uint32_t)(row * PITCH + kcol * 2);
    }
    #pragma unroll
    for (int q = 0; q < 4; q++) {
        int n0   = noff + q * 16;
        int row  = n0 + ((mt8 >> 1) << 3) + mr;
        int kcol = (mt8 & 1) << 3;
        boff[q] = (uint32_t)(row * PITCH + kcol * 2);
    }
    const uint32_t Abase = sb + SM_PLANE;
    const uint32_t Bbase = sb + SM_PLANE + 3 * PLB;

    float cM[2][8][4], cC[2][8][4];
    #pragma unroll
    for (int i = 0; i < 2; i++)
        #pragma unroll
        for (int j = 0; j < 8; j++)
            #pragma unroll
            for (int q = 0; q < 4; q++) { cM[i][j][q] = 0.0f; cC[i][j][q] = 0.0f; }

    // prefetch chunk 0
    float4 fa0 = *reinterpret_cast<const float4*>(gA);
    float4 fa1 = *reinterpret_cast<const float4*>(gA + 4);
    float4 fb0 = *reinterpret_cast<const float4*>(gB);
    float4 fb1 = *reinterpret_cast<const float4*>(gB + 4);

    for (int c = 0; c < NCH; c++) {
        __syncthreads();                       // prev chunk's ldmatrix done

        cvt8(fa0, fa1, pA, pA + PLB, pA + 2 * PLB);
        cvt8(fb0, fb1, pB, pB + PLB, pB + 2 * PLB);

        if (c + 1 < NCH) {                     // prefetch next (hidden by MMA)
            const float* a = gA + (c + 1) * KC;
            const float* b = gB + (c + 1) * KC;
            fa0 = *reinterpret_cast<const float4*>(a);
            fa1 = *reinterpret_cast<const float4*>(a + 4);
            fb0 = *reinterpret_cast<const float4*>(b);
            fb1 = *reinterpret_cast<const float4*>(b + 4);
        }

        __syncthreads();                       // stage fully written

        uint32_t Af[2][4], Bf[16];
        // B-plane 0: products A0->cM, A1->cC, A2->cC
        #pragma unroll
        for (int q = 0; q < 4; q++) ldmx4(&Bf[q * 4], Bbase + boff[q]);
        #pragma unroll
        for (int mt = 0; mt < 2; mt++) ldmx4(Af[mt], Abase + aoff[mt]);
        #pragma unroll
        for (int mt = 0; mt < 2; mt++)
            #pragma unroll
            for (int nt = 0; nt < 8; nt++) mma16(cM[mt][nt], Af[mt], &Bf[nt * 2]);
        #pragma unroll
        for (int mt = 0; mt < 2; mt++) ldmx4(Af[mt], Abase + PLB + aoff[mt]);
        #pragma unroll
        for (int mt = 0; mt < 2; mt++)
            #pragma unroll
            for (int nt = 0; nt < 8; nt++) mma16(cC[mt][nt], Af[mt], &Bf[nt * 2]);
        #pragma unroll
        for (int mt = 0; mt < 2; mt++) ldmx4(Af[mt], Abase + 2 * PLB + aoff[mt]);
        #pragma unroll
        for (int mt = 0; mt < 2; mt++)
            #pragma unroll
            for (int nt = 0; nt < 8; nt++) mma16(cC[mt][nt], Af[mt], &Bf[nt * 2]);

        // B-plane 1: products A0->cC, A1->cC
        #pragma unroll
        for (int q = 0; q < 4; q++) ldmx4(&Bf[q * 4], Bbase + PLB + boff[q]);
        #pragma unroll
        for (int mt = 0; mt < 2; mt++) ldmx4(Af[mt], Abase + aoff[mt]);
        #pragma unroll
        for (int mt = 0; mt < 2; mt++)
            #pragma unroll
            for (int nt = 0; nt < 8; nt++) mma16(cC[mt][nt], Af[mt], &Bf[nt * 2]);
        #pragma unroll
        for (int mt = 0; mt < 2; mt++) ldmx4(Af[mt], Abase + PLB + aoff[mt]);
        #pragma unroll
        for (int mt = 0; mt < 2; mt++)
            #pragma unroll
            for (int nt = 0; nt < 8; nt++) mma16(cC[mt][nt], Af[mt], &Bf[nt * 2]);

        // B-plane 2: product A0->cC
        #pragma unroll
        for (int q = 0; q < 4; q++) ldmx4(&Bf[q * 4], Bbase + 2 * PLB + boff[q]);
        #pragma unroll
        for (int mt = 0; mt < 2; mt++) ldmx4(Af[mt], Abase + aoff[mt]);
        #pragma unroll
        for (int mt = 0; mt < 2; mt++)
            #pragma unroll
            for (int nt = 0; nt < 8; nt++) mma16(cC[mt][nt], Af[mt], &Bf[nt * 2]);
    }

    __syncthreads();   // all ldmatrix done; plane SMEM now reusable for logits

    // ---- combine accumulators, write logits [128][132] ----
    #pragma unroll
    for (int mt = 0; mt < 2; mt++)
        #pragma unroll
        for (int nt = 0; nt < 8; nt++) {
            int r0  = moff + mt * 16 + (lane >> 2);
            int col = noff + nt * 8 + 2 * (lane & 3);
            slog[r0 * LPITCH + col]           = cM[mt][nt][0] + cC[mt][nt][0];
            slog[r0 * LPITCH + col + 1]       = cM[mt][nt][1] + cC[mt][nt][1];
            slog[(r0 + 8) * LPITCH + col]     = cM[mt][nt][2] + cC[mt][nt][2];
            slog[(r0 + 8) * LPITCH + col + 1] = cM[mt][nt][3] + cC[mt][nt][3];
        }

    __syncthreads();

    // ---- top-4 + softmax: one thread per token ----
    if (tid < BM) {
        const float* row = slog + tid * LPITCH;
        float v0 = -1e30f, v1 = -1e30f, v2 = -1e30f, v3 = -1e30f;
        int   i0 = 0,      i1 = 0,      i2 = 0,      i3 = 0;
        #pragma unroll 4
        for (int e = 0; e < EE; e++) {
            float v = row[e] + sbias[e];
            if (v > v3) {               // strict > keeps earliest index on ties
                if (v > v2) {
                    v3 = v2; i3 = i2;
                    if (v > v1) {
                        v2 = v1; i2 = i1;
                        if (v > v0) { v1 = v0; i1 = i0; v0 = v; i0 = e; }
                        else        { v1 = v;  i1 = e; }
                    } else { v2 = v; i2 = e; }
                } else { v3 = v; i3 = e; }
            }
        }
        float e1 = expf(v1 - v0);
        float e2 = expf(v2 - v0);
        float e3 = expf(v3 - v0);
        float inv = 1.0f / (1.0f + e1 + e2 + e3);

        const int t = m0 + tid;
        float* so = out + (size_t)t * TOPK;
        so[0] = inv; so[1] = e1 * inv; so[2] = e2 * inv; so[3] = e3 * inv;
        if (write_idx) {
            float* io = out + (size_t)TT * TOPK + (size_t)t * TOPK;
            io[0] = (float)i0; io[1] = (float)i1;
            io[2] = (float)i2; io[3] = (float)i3;
        }
    }
}

extern "C" void kernel_launch(void* const* d_in, const int* in_sizes, int n_in,
                              void* d_out, int out_size) {
    const float* hs   = (const float*)d_in[0];
    const float* wt   = (const float*)d_in[1];
    const float* bias = (const float*)d_in[2];
    float* out = (float*)d_out;

    const int write_idx = (out_size >= 2 * TT * TOPK) ? 1 : 0;

    cudaFuncSetAttribute(router_hmma,
                         cudaFuncAttributeMaxDynamicSharedMemorySize, SMEM_BYTES);
    router_hmma<<<TT / BM, 256, SMEM_BYTES>>>(hs, wt, bias, out, write_idx);
}

// round 7
// speedup vs baseline: 3.1827x; 1.1731x over previous
#include <cuda_runtime.h>
#include <cstdint>

// GptOssTopKRouter via mma.sync bf16 (compute_103-safe tensor path).
// logits = hs[16384,2880] @ w[128,2880]^T + bias -> top-4 -> softmax.
// Output f32: scores[T*4] ++ indices[T*4].
//
// fp32 via 3-plane bf16 Dekker split, 6 plane-products. Main product (a0b0)
// in its own fp32 accumulator set; corrections in a second set.
// R7: 512 threads (16 warps, warp tile 16x64), 2-stage SMEM ping-pong with
// ONE barrier per chunk; cvt(c+1) overlaps MMA(c); depth-2 LDG prefetch.

#define TT    16384
#define HH    2880
#define EE    128
#define TOPK  4
#define BM    128
#define KC    16
#define NCH   (HH / KC)        // 180

#define PITCH  48              // bytes/row in a bf16 plane (16-aligned, conflict-free)
#define PLB    (128 * PITCH)   // 6144 B per plane
#define STG    (6 * PLB)       // A0 A1 A2 B0 B1 B2 = 36864 B
#define SMOFF  512
#define LPITCH 132
#define SMEM_BYTES (SMOFF + 2 * STG)   // 74240 (logits reuse stage area)

__device__ __forceinline__ uint32_t s2u(const void* p) {
    uint32_t a;
    asm("{ .reg .u64 t; cvta.to.shared.u64 t, %1; cvt.u32.u64 %0, t; }"
        : "=r"(a) : "l"(p));
    return a;
}
__device__ __forceinline__ uint32_t pack_bf16x2(float hi, float lo) {
    uint32_t r;
    asm("cvt.rn.bf16x2.f32 %0, %1, %2;" : "=r"(r) : "f"(hi), "f"(lo));
    return r;
}
__device__ __forceinline__ void ldmx4(uint32_t* r, uint32_t addr) {
    asm volatile("ldmatrix.sync.aligned.m8n8.x4.shared.b16 {%0,%1,%2,%3}, [%4];"
                 : "=r"(r[0]), "=r"(r[1]), "=r"(r[2]), "=r"(r[3]) : "r"(addr));
}
__device__ __forceinline__ void mma16(float* c, const uint32_t* a, const uint32_t* b) {
    asm("mma.sync.aligned.m16n8k16.row.col.f32.bf16.bf16.f32 "
        "{%0,%1,%2,%3}, {%4,%5,%6,%7}, {%8,%9}, {%0,%1,%2,%3};"
        : "+f"(c[0]), "+f"(c[1]), "+f"(c[2]), "+f"(c[3])
        : "r"(a[0]), "r"(a[1]), "r"(a[2]), "r"(a[3]), "r"(b[0]), "r"(b[1]));
}

// 4 fp32 -> 3 bf16 planes (Dekker exact split), one 8B store per plane.
__device__ __forceinline__ void cvt4(const float4& f, char* p0, char* p1, char* p2) {
    float x[4] = {f.x, f.y, f.z, f.w};
    uint32_t q0[2], q1[2], q2[2];
    #pragma unroll
    for (int q = 0; q < 2; q++) {
        float a = x[2 * q], b = x[2 * q + 1];
        uint32_t h = pack_bf16x2(b, a);
        float ha = __uint_as_float(h << 16);
        float hb = __uint_as_float(h & 0xFFFF0000u);
        float ra = a - ha, rb = b - hb;            // exact
        uint32_t m = pack_bf16x2(rb, ra);
        float ma = __uint_as_float(m << 16);
        float mb = __uint_as_float(m & 0xFFFF0000u);
        q2[q] = pack_bf16x2(rb - mb, ra - ma);     // exact residual
        q0[q] = h; q1[q] = m;
    }
    *reinterpret_cast<uint2*>(p0) = make_uint2(q0[0], q0[1]);
    *reinterpret_cast<uint2*>(p1) = make_uint2(q1[0], q1[1]);
    *reinterpret_cast<uint2*>(p2) = make_uint2(q2[0], q2[1]);
}

__global__ __launch_bounds__(512, 1)
void router_hmma(const float* __restrict__ hs,
                 const float* __restrict__ wt,
                 const float* __restrict__ bias,
                 float* __restrict__ out,
                 int write_idx)
{
    extern __shared__ char smem[];
    float* sbias = reinterpret_cast<float*>(smem);
    float* slog  = reinterpret_cast<float*>(smem + SMOFF);
    const uint32_t sb = s2u(smem);

    const int tid  = threadIdx.x;
    const int wid  = tid >> 5;
    const int lane = tid & 31;
    const int m0   = blockIdx.x * BM;

    if (tid < EE) sbias[tid] = bias[tid];

    // ---- convert mapping: 4 threads per row, 4 fp32 each ----
    const int crow = tid >> 2;
    const int ckq  = (tid & 3) * 4;
    const float* gA = hs + (size_t)(m0 + crow) * HH + ckq;
    const float* gB = wt + (size_t)crow * HH + ckq;
    const int cvtoff = crow * PITCH + ckq * 2;

    // ---- mma mapping: 16 warps = 8M x 2N; warp tile 16x64 ----
    const int moff = (wid >> 1) * 16;
    const int noff = (wid & 1) * 64;
    const int mt8  = lane >> 3;
    const int mr   = lane & 7;
    const uint32_t aoff =
        (uint32_t)((moff + ((mt8 & 1) << 3) + mr) * PITCH + (((mt8 >> 1) << 3) << 1));
    uint32_t boff[4];
    #pragma unroll
    for (int q = 0; q < 4; q++) {
        int row  = noff + q * 16 + ((mt8 >> 1) << 3) + mr;
        int kcol = (mt8 & 1) << 3;
        boff[q] = (uint32_t)(row * PITCH + kcol * 2);
    }

    float cM[8][4], cC[8][4];
    #pragma unroll
    for (int j = 0; j < 8; j++)
        #pragma unroll
        for (int q = 0; q < 4; q++) { cM[j][q] = 0.0f; cC[j][q] = 0.0f; }

    // ---- prologue: LDG(0), cvt->stage0, LDG(1) ----
    float4 pfa = *reinterpret_cast<const float4*>(gA);
    float4 pfb = *reinterpret_cast<const float4*>(gB);
    {
        char* st = smem + SMOFF;
        cvt4(pfa, st + cvtoff, st + PLB + cvtoff, st + 2 * PLB + cvtoff);
        char* stB = st + 3 * PLB;
        cvt4(pfb, stB + cvtoff, stB + PLB + cvtoff, stB + 2 * PLB + cvtoff);
    }
    pfa = *reinterpret_cast<const float4*>(gA + KC);
    pfb = *reinterpret_cast<const float4*>(gB + KC);
    __syncthreads();

    for (int c = 0; c < NCH; c++) {
        const int s = c & 1;
        const uint32_t Ab = sb + SMOFF + s * STG;
        const uint32_t Bb = Ab + 3 * PLB;

        // A planes (resident for the whole chunk)
        uint32_t A0[4], A1[4], A2[4], Bf[16];
        ldmx4(A0, Ab + aoff);
        ldmx4(A1, Ab + PLB + aoff);
        ldmx4(A2, Ab + 2 * PLB + aoff);

        // B plane 0: A0->cM, A1->cC, A2->cC
        #pragma unroll
        for (int q = 0; q < 4; q++) ldmx4(&Bf[q * 4], Bb + boff[q]);
        #pragma unroll
        for (int nt = 0; nt < 8; nt++) mma16(cM[nt], A0, &Bf[nt * 2]);
        #pragma unroll
        for (int nt = 0; nt < 8; nt++) mma16(cC[nt], A1, &Bf[nt * 2]);
        #pragma unroll
        for (int nt = 0; nt < 8; nt++) mma16(cC[nt], A2, &Bf[nt * 2]);

        // overlapped: convert chunk c+1 into the other stage
        if (c + 1 < NCH) {
            char* st  = smem + SMOFF + (s ^ 1) * STG;
            char* stB = st + 3 * PLB;
            cvt4(pfa, st + cvtoff, st + PLB + cvtoff, st + 2 * PLB + cvtoff);
            cvt4(pfb, stB + cvtoff, stB + PLB + cvtoff, stB + 2 * PLB + cvtoff);
        }
        if (c + 2 < NCH) {                    // depth-2 prefetch
            pfa = *reinterpret_cast<const float4*>(gA + (size_t)(c + 2) * KC);
            pfb = *reinterpret_cast<const float4*>(gB + (size_t)(c + 2) * KC);
        }

        // B plane 1: A0->cC, A1->cC
        #pragma unroll
        for (int q = 0; q < 4; q++) ldmx4(&Bf[q * 4], Bb + PLB + boff[q]);
        #pragma unroll
        for (int nt = 0; nt < 8; nt++) mma16(cC[nt], A0, &Bf[nt * 2]);
        #pragma unroll
        for (int nt = 0; nt < 8; nt++) mma16(cC[nt], A1, &Bf[nt * 2]);

        // B plane 2: A0->cC
        #pragma unroll
        for (int q = 0; q < 4; q++) ldmx4(&Bf[q * 4], Bb + 2 * PLB + boff[q]);
        #pragma unroll
        for (int nt = 0; nt < 8; nt++) mma16(cC[nt], A0, &Bf[nt * 2]);

        __syncthreads();   // stage s reads done; stage s^1 writes visible
    }

    // ---- combine accumulators, write logits [128][132] (stage area reused) ----
    #pragma unroll
    for (int nt = 0; nt < 8; nt++) {
        int r0  = moff + (lane >> 2);
        int col = noff + nt * 8 + 2 * (lane & 3);
        slog[r0 * LPITCH + col]           = cM[nt][0] + cC[nt][0];
        slog[r0 * LPITCH + col + 1]       = cM[nt][1] + cC[nt][1];
        slog[(r0 + 8) * LPITCH + col]     = cM[nt][2] + cC[nt][2];
        slog[(r0 + 8) * LPITCH + col + 1] = cM[nt][3] + cC[nt][3];
    }

    __syncthreads();

    // ---- top-4 + softmax: one thread per token ----
    if (tid < BM) {
        const float* row = slog + tid * LPITCH;
        float v0 = -1e30f, v1 = -1e30f, v2 = -1e30f, v3 = -1e30f;
        int   i0 = 0,      i1 = 0,      i2 = 0,      i3 = 0;
        #pragma unroll 4
        for (int e = 0; e < EE; e++) {
            float v = row[e] + sbias[e];
            if (v > v3) {               // strict > keeps earliest index on ties
                if (v > v2) {
                    v3 = v2; i3 = i2;
                    if (v > v1) {
                        v2 = v1; i2 = i1;
                        if (v > v0) { v1 = v0; i1 = i0; v0 = v; i0 = e; }
                        else        { v1 = v;  i1 = e; }
                    } else { v2 = v; i2 = e; }
                } else { v3 = v; i3 = e; }
            }
        }
        float e1 = expf(v1 - v0);
        float e2 = expf(v2 - v0);
        float e3 = expf(v3 - v0);
        float inv = 1.0f / (1.0f + e1 + e2 + e3);

        const int t = m0 + tid;
        float* so = out + (size_t)t * TOPK;
        so[0] = inv; so[1] = e1 * inv; so[2] = e2 * inv; so[3] = e3 * inv;
        if (write_idx) {
            float* io = out + (size_t)TT * TOPK + (size_t)t * TOPK;
            io[0] = (float)i0; io[1] = (float)i1;
            io[2] = (float)i2; io[3] = (float)i3;
        }
    }
}

extern "C" void kernel_launch(void* const* d_in, const int* in_sizes, int n_in,
                              void* d_out, int out_size) {
    const float* hs   = (const float*)d_in[0];
    const float* wt   = (const float*)d_in[1];
    const float* bias = (const float*)d_in[2];
    float* out = (float*)d_out;

    const int write_idx = (out_size >= 2 * TT * TOPK) ? 1 : 0;

    cudaFuncSetAttribute(router_hmma,
                         cudaFuncAttributeMaxDynamicSharedMemorySize, SMEM_BYTES);
    router_hmma<<<TT / BM, 512, SMEM_BYTES>>>(hs, wt, bias, out, write_idx);
}

// round 8
// speedup vs baseline: 3.3525x; 1.0533x over previous
#include <cuda_runtime.h>
#include <cstdint>

// GptOssTopKRouter via mma.sync bf16 (compute_103-safe tensor path).
// logits = hs[16384,2880] @ w[128,2880]^T + bias -> top-4 -> softmax.
// Output f32: scores[T*4] ++ indices[T*4].
//
// fp32 via 3-plane bf16 Dekker split, 6 plane-products; main product (a0b0)
// in its own fp32 accumulator set, corrections in a second set.
// R8: 4Mx4N warp grid (warp tile 32x32 -> minimal ldmatrix duplication),
// KC=32 chunks (90 barriers), PITCH=80 conflict-free layout, 2-stage
// ping-pong with cvt(c+1) overlapping MMA(c).

#define TT    16384
#define HH    2880
#define EE    128
#define TOPK  4
#define BM    128
#define KC    32
#define NCH   (HH / KC)        // 90

#define PITCH  80              // bytes/row (odd multiple of 16 -> conflict-free)
#define PLB    (128 * PITCH)   // 10240 B per plane
#define STG    (6 * PLB)       // A0 A1 A2 B0 B1 B2 = 61440 B
#define SMOFF  512
#define LPITCH 132
#define SMEM_BYTES (SMOFF + 2 * STG)   // 123392 (logits reuse stage area)

__device__ __forceinline__ uint32_t s2u(const void* p) {
    uint32_t a;
    asm("{ .reg .u64 t; cvta.to.shared.u64 t, %1; cvt.u32.u64 %0, t; }"
        : "=r"(a) : "l"(p));
    return a;
}
__device__ __forceinline__ uint32_t pack_bf16x2(float hi, float lo) {
    uint32_t r;
    asm("cvt.rn.bf16x2.f32 %0, %1, %2;" : "=r"(r) : "f"(hi), "f"(lo));
    return r;
}
__device__ __forceinline__ void ldmx4(uint32_t* r, uint32_t addr) {
    asm volatile("ldmatrix.sync.aligned.m8n8.x4.shared.b16 {%0,%1,%2,%3}, [%4];"
                 : "=r"(r[0]), "=r"(r[1]), "=r"(r[2]), "=r"(r[3]) : "r"(addr));
}
__device__ __forceinline__ void mma16(float* c, const uint32_t* a, const uint32_t* b) {
    asm("mma.sync.aligned.m16n8k16.row.col.f32.bf16.bf16.f32 "
        "{%0,%1,%2,%3}, {%4,%5,%6,%7}, {%8,%9}, {%0,%1,%2,%3};"
        : "+f"(c[0]), "+f"(c[1]), "+f"(c[2]), "+f"(c[3])
        : "r"(a[0]), "r"(a[1]), "r"(a[2]), "r"(a[3]), "r"(b[0]), "r"(b[1]));
}

// 8 fp32 -> 3 bf16 planes (Dekker exact split), one 16B store per plane.
__device__ __forceinline__ void cvt8(const float4& f0, const float4& f1,
                                     char* p0, char* p1, char* p2) {
    float x[8] = {f0.x, f0.y, f0.z, f0.w, f1.x, f1.y, f1.z, f1.w};
    uint32_t q0[4], q1[4], q2[4];
    #pragma unroll
    for (int q = 0; q < 4; q++) {
        float a = x[2 * q], b = x[2 * q + 1];
        uint32_t h = pack_bf16x2(b, a);             // lo=bf16(a), hi=bf16(b)
        float ha = __uint_as_float(h << 16);
        float hb = __uint_as_float(h & 0xFFFF0000u);
        float ra = a - ha, rb = b - hb;             // exact
        uint32_t m = pack_bf16x2(rb, ra);
        float ma = __uint_as_float(m << 16);
        float mb = __uint_as_float(m & 0xFFFF0000u);
        q2[q] = pack_bf16x2(rb - mb, ra - ma);      // exact residual
        q0[q] = h; q1[q] = m;
    }
    *reinterpret_cast<uint4*>(p0) = make_uint4(q0[0], q0[1], q0[2], q0[3]);
    *reinterpret_cast<uint4*>(p1) = make_uint4(q1[0], q1[1], q1[2], q1[3]);
    *reinterpret_cast<uint4*>(p2) = make_uint4(q2[0], q2[1], q2[2], q2[3]);
}

__global__ __launch_bounds__(512, 1)
void router_hmma(const float* __restrict__ hs,
                 const float* __restrict__ wt,
                 const float* __restrict__ bias,
                 float* __restrict__ out,
                 int write_idx)
{
    extern __shared__ char smem[];
    float* sbias = reinterpret_cast<float*>(smem);
    float* slog  = reinterpret_cast<float*>(smem + SMOFF);
    const uint32_t sb = s2u(smem);

    const int tid  = threadIdx.x;
    const int wid  = tid >> 5;
    const int lane = tid & 31;
    const int m0   = blockIdx.x * BM;

    if (tid < EE) sbias[tid] = bias[tid];

    // ---- convert mapping: 4 threads per row, 8 fp32 each (KC=32) ----
    const int crow = tid >> 2;
    const int ckq  = (tid & 3) * 8;
    const float* gA = hs + (size_t)(m0 + crow) * HH + ckq;
    const float* gB = wt + (size_t)crow * HH + ckq;
    const int cvtoff = crow * PITCH + ckq * 2;

    // ---- mma mapping: 16 warps = 4M x 4N; warp tile 32x32 ----
    const int moff = (wid & 3) * 32;
    const int noff = (wid >> 2) * 32;
    const int mt8  = lane >> 3;
    const int mr   = lane & 7;
    uint32_t aoff[2], boff[2];
    #pragma unroll
    for (int mt = 0; mt < 2; mt++)
        aoff[mt] = (uint32_t)((moff + mt * 16 + ((mt8 & 1) << 3) + mr) * PITCH
                              + (((mt8 >> 1) << 3) << 1));
    #pragma unroll
    for (int q = 0; q < 2; q++)
        boff[q] = (uint32_t)((noff + q * 16 + ((mt8 >> 1) << 3) + mr) * PITCH
                             + (((mt8 & 1) << 3) << 1));

    float cM[2][4][4], cC[2][4][4];
    #pragma unroll
    for (int i = 0; i < 2; i++)
        #pragma unroll
        for (int j = 0; j < 4; j++)
            #pragma unroll
            for (int q = 0; q < 4; q++) { cM[i][j][q] = 0.0f; cC[i][j][q] = 0.0f; }

    // ---- prologue: LDG(0), cvt->stage0, LDG(1) ----
    float4 pa0 = *reinterpret_cast<const float4*>(gA);
    float4 pa1 = *reinterpret_cast<const float4*>(gA + 4);
    float4 pb0 = *reinterpret_cast<const float4*>(gB);
    float4 pb1 = *reinterpret_cast<const float4*>(gB + 4);
    {
        char* st  = smem + SMOFF;
        char* stB = st + 3 * PLB;
        cvt8(pa0, pa1, st + cvtoff, st + PLB + cvtoff, st + 2 * PLB + cvtoff);
        cvt8(pb0, pb1, stB + cvtoff, stB + PLB + cvtoff, stB + 2 * PLB + cvtoff);
    }
    pa0 = *reinterpret_cast<const float4*>(gA + KC);
    pa1 = *reinterpret_cast<const float4*>(gA + KC + 4);
    pb0 = *reinterpret_cast<const float4*>(gB + KC);
    pb1 = *reinterpret_cast<const float4*>(gB + KC + 4);
    __syncthreads();

    for (int c = 0; c < NCH; c++) {
        const int s = c & 1;
        const uint32_t Ab = sb + SMOFF + s * STG;
        const uint32_t Bb = Ab + 3 * PLB;

        #pragma unroll
        for (int ks = 0; ks < 2; ks++) {
            const uint32_t kb = ks * 32;       // 16 K-cols = 32 bytes

            uint32_t A0[2][4], A1[2][4], A2[2][4], Bf[8];
            #pragma unroll
            for (int mt = 0; mt < 2; mt++) ldmx4(A0[mt], Ab + aoff[mt] + kb);
            #pragma unroll
            for (int mt = 0; mt < 2; mt++) ldmx4(A1[mt], Ab + PLB + aoff[mt] + kb);
            #pragma unroll
            for (int mt = 0; mt < 2; mt++) ldmx4(A2[mt], Ab + 2 * PLB + aoff[mt] + kb);

            // B plane 0: A0->cM, A1->cC, A2->cC
            #pragma unroll
            for (int q = 0; q < 2; q++) ldmx4(&Bf[q * 4], Bb + boff[q] + kb);
            #pragma unroll
            for (int mt = 0; mt < 2; mt++)
                #pragma unroll
                for (int nt = 0; nt < 4; nt++) {
                    mma16(cM[mt][nt], A0[mt], &Bf[nt * 2]);
                    mma16(cC[mt][nt], A1[mt], &Bf[nt * 2]);
                    mma16(cC[mt][nt], A2[mt], &Bf[nt * 2]);
                }

            // overlapped work in first k-step: cvt(c+1) + prefetch(c+2)
            if (ks == 0) {
                if (c + 1 < NCH) {
                    char* st  = smem + SMOFF + (s ^ 1) * STG;
                    char* stB = st + 3 * PLB;
                    cvt8(pa0, pa1, st + cvtoff, st + PLB + cvtoff,
                         st + 2 * PLB + cvtoff);
                    cvt8(pb0, pb1, stB + cvtoff, stB + PLB + cvtoff,
                         stB + 2 * PLB + cvtoff);
                }
                if (c + 2 < NCH) {
                    const float* a = gA + (size_t)(c + 2) * KC;
                    const float* b = gB + (size_t)(c + 2) * KC;
                    pa0 = *reinterpret_cast<const float4*>(a);
                    pa1 = *reinterpret_cast<const float4*>(a + 4);
                    pb0 = *reinterpret_cast<const float4*>(b);
                    pb1 = *reinterpret_cast<const float4*>(b + 4);
                }
            }

            // B plane 1: A0->cC, A1->cC
            #pragma unroll
            for (int q = 0; q < 2; q++) ldmx4(&Bf[q * 4], Bb + PLB + boff[q] + kb);
            #pragma unroll
            for (int mt = 0; mt < 2; mt++)
                #pragma unroll
                for (int nt = 0; nt < 4; nt++) {
                    mma16(cC[mt][nt], A0[mt], &Bf[nt * 2]);
                    mma16(cC[mt][nt], A1[mt], &Bf[nt * 2]);
                }

            // B plane 2: A0->cC
            #pragma unroll
            for (int q = 0; q < 2; q++) ldmx4(&Bf[q * 4], Bb + 2 * PLB + boff[q] + kb);
            #pragma unroll
            for (int mt = 0; mt < 2; mt++)
                #pragma unroll
                for (int nt = 0; nt < 4; nt++)
                    mma16(cC[mt][nt], A0[mt], &Bf[nt * 2]);
        }

        __syncthreads();   // stage s reads done; stage s^1 writes visible
    }

    // ---- combine accumulators, write logits [128][132] (stage area reused) ----
    #pragma unroll
    for (int mt = 0; mt < 2; mt++)
        #pragma unroll
        for (int nt = 0; nt < 4; nt++) {
            int r0  = moff + mt * 16 + (lane >> 2);
            int col = noff + nt * 8 + 2 * (lane & 3);
            slog[r0 * LPITCH + col]           = cM[mt][nt][0] + cC[mt][nt][0];
            slog[r0 * LPITCH + col + 1]       = cM[mt][nt][1] + cC[mt][nt][1];
            slog[(r0 + 8) * LPITCH + col]     = cM[mt][nt][2] + cC[mt][nt][2];
            slog[(r0 + 8) * LPITCH + col + 1] = cM[mt][nt][3] + cC[mt][nt][3];
        }

    __syncthreads();

    // ---- top-4 + softmax: one thread per token ----
    if (tid < BM) {
        const float* row = slog + tid * LPITCH;
        float v0 = -1e30f, v1 = -1e30f, v2 = -1e30f, v3 = -1e30f;
        int   i0 = 0,      i1 = 0,      i2 = 0,      i3 = 0;
        #pragma unroll 4
        for (int e = 0; e < EE; e++) {
            float v = row[e] + sbias[e];
            if (v > v3) {               // strict > keeps earliest index on ties
                if (v > v2) {
                    v3 = v2; i3 = i2;
                    if (v > v1) {
                        v2 = v1; i2 = i1;
                        if (v > v0) { v1 = v0; i1 = i0; v0 = v; i0 = e; }
                        else        { v1 = v;  i1 = e; }
                    } else { v2 = v; i2 = e; }
                } else { v3 = v; i3 = e; }
            }
        }
        float e1 = expf(v1 - v0);
        float e2 = expf(v2 - v0);
        float e3 = expf(v3 - v0);
        float inv = 1.0f / (1.0f + e1 + e2 + e3);

        const int t = m0 + tid;
        float* so = out + (size_t)t * TOPK;
        so[0] = inv; so[1] = e1 * inv; so[2] = e2 * inv; so[3] = e3 * inv;
        if (write_idx) {
            float* io = out + (size_t)TT * TOPK + (size_t)t * TOPK;
            io[0] = (float)i0; io[1] = (float)i1;
            io[2] = (float)i2; io[3] = (float)i3;
        }
    }
}

extern "C" void kernel_launch(void* const* d_in, const int* in_sizes, int n_in,
                              void* d_out, int out_size) {
    const float* hs   = (const float*)d_in[0];
    const float* wt   = (const float*)d_in[1];
    const float* bias = (const float*)d_in[2];
    float* out = (float*)d_out;

    const int write_idx = (out_size >= 2 * TT * TOPK) ? 1 : 0;

    cudaFuncSetAttribute(router_hmma,
                         cudaFuncAttributeMaxDynamicSharedMemorySize, SMEM_BYTES);
    router_hmma<<<TT / BM, 512, SMEM_BYTES>>>(hs, wt, bias, out, write_idx);
}